// round 6
// baseline (speedup 1.0000x reference)
#include <cuda_runtime.h>
#include <cuda_bf16.h>
#include <cstdint>

// Problem constants (fixed by the reference)
#define N_COLS  22
#define N_PAIRS 231
#define EMB     12
#define DVEC    64
#define N_PRIM  5
#define COMBO2  (EMB * EMB * 2)   // 288 floats per pair in the LUT
#define NCHUNK  8                 // pair-dimension split for kernel 2
#define CHUNKSZ ((N_PAIRS + NCHUNK - 1) / NCHUNK)   // 29
#define BT      128               // batch tile per block in kernel 2

// Scratch: precomputed per-pair lookup table T[p][fi][fj][o]  (266 KB)
__device__ __align__(16) float g_T[N_PAIRS * COMBO2];

// ---------------------------------------------------------------------------
// Kernel 1: build T[p, fi, fj, o] = sum_d w_sel[p,o,d] * op_sel(ti[fi,d], tj[fj,d])
// One block per pair; 288 threads, one per (fi, fj, o) task. float4 staging +
// float4 inner loop. Also zero-initializes out[] so kernel 2 can atomicAdd.
// ---------------------------------------------------------------------------
#define ROWSTRIDE (DVEC + 4)      // 68 floats: float4-aligned, shifts banks by 4/row

__global__ __launch_bounds__(COMBO2)
void build_lut_kernel(const float* __restrict__ tables,
                      const float* __restrict__ Wsmall,
                      const float* __restrict__ Wconcat,
                      const float* __restrict__ aw,
                      float* __restrict__ out, int outN)
{
    const int p = blockIdx.x;

    // zero the output buffer (poisoned by harness); same-stream ordering makes
    // this visible to kernel 2's atomics
    for (int e = blockIdx.x * COMBO2 + threadIdx.x; e < outN; e += gridDim.x * COMBO2)
        out[e] = 0.0f;

    // pair p -> (i, j) of triu(N_COLS, k=1), row-major order
    int i = 0, r = p, c = N_COLS - 1;
    while (r >= c) { r -= c; ++i; --c; }
    const int j = i + 1 + r;

    // selected primitive (arch_weights is exact one-hot of 0.0 / 1.0)
    int k = 0;
#pragma unroll
    for (int t = 0; t < N_PRIM; ++t)
        if (aw[p * N_PRIM + t] > 0.5f) k = t;

    // stage the 12 candidate embedding vectors for columns i and j (float4)
    __shared__ float shi[EMB * ROWSTRIDE];
    __shared__ float shj[EMB * ROWSTRIDE];
    {
        const float4* __restrict__ t4 = (const float4*)tables;
        for (int e = threadIdx.x; e < 2 * EMB * (DVEC / 4); e += blockDim.x) {
            const int which = (e >= EMB * (DVEC / 4));
            const int e2  = e - which * EMB * (DVEC / 4);
            const int row = e2 >> 4, d4 = e2 & 15;
            const float4 v = __ldg(&t4[((which ? j : i) * EMB + row) * (DVEC / 4) + d4]);
            float* dst = which ? shj : shi;
            ((float4*)dst)[row * (ROWSTRIDE / 4) + d4] = v;
        }
    }
    __syncthreads();

    const int task  = threadIdx.x;          // 0..287
    const int o     = task & 1;
    const int combo = task >> 1;            // fi*12 + fj
    const int fi    = combo / EMB;
    const int fj    = combo - fi * EMB;

    const float4* __restrict__ pi = (const float4*)&shi[fi * ROWSTRIDE];
    const float4* __restrict__ pj = (const float4*)&shj[fj * ROWSTRIDE];

    float acc = 0.0f;
    if (k == 4) {
        const float4* __restrict__ wa = (const float4*)(Wconcat + (p * 2 + o) * (2 * DVEC));
        const float4* __restrict__ wb = wa + (DVEC / 4);
#pragma unroll
        for (int d = 0; d < DVEC / 4; ++d) {
            const float4 a = pi[d], b = pj[d];
            const float4 u = __ldg(&wa[d]), v = __ldg(&wb[d]);
            acc += u.x * a.x + u.y * a.y + u.z * a.z + u.w * a.w;
            acc += v.x * b.x + v.y * b.y + v.z * b.z + v.w * b.w;
        }
    } else {
        const float4* __restrict__ w = (const float4*)(Wsmall + ((p * 4 + k) * 2 + o) * DVEC);
#pragma unroll
        for (int d = 0; d < DVEC / 4; ++d) {
            const float4 a = pi[d], b = pj[d];
            const float4 u = __ldg(&w[d]);
            float4 z;
            if (k == 0)      { z.x = a.x + b.x; z.y = a.y + b.y; z.z = a.z + b.z; z.w = a.w + b.w; }
            else if (k == 1) { z.x = a.x * b.x; z.y = a.y * b.y; z.z = a.z * b.z; z.w = a.w * b.w; }
            else if (k == 2) { z.x = fmaxf(a.x, b.x); z.y = fmaxf(a.y, b.y); z.z = fmaxf(a.z, b.z); z.w = fmaxf(a.w, b.w); }
            else             { z.x = fminf(a.x, b.x); z.y = fminf(a.y, b.y); z.z = fminf(a.z, b.z); z.w = fminf(a.w, b.w); }
            acc += u.x * z.x + u.y * z.y + u.z * z.z + u.w * z.w;
        }
    }
    g_T[p * COMBO2 + combo * 2 + o] = acc;
}

// ---------------------------------------------------------------------------
// Kernel 2: out[b, :] += sum_{p in chunk} T[p, f[i_p], f[j_p], :]
// grid = (B/128) x 8 chunks. Block stages its 29-pair LUT slice (33.4 KB,
// contiguous in g_T) into SMEM, then gathers with LDS.64 — no exposed L2
// latency. warp = (batch subtile of 32, pair stripe of 2). Intra-block reduce
// via SMEM; cross-chunk combine via atomicAdd (out zeroed by kernel 1).
// ---------------------------------------------------------------------------
__global__ __launch_bounds__(256)
void accumulate_kernel(const int* __restrict__ feats,
                       float* __restrict__ out,
                       int B)
{
    __shared__ float2 slut[CHUNKSZ * EMB * EMB];   // 29 * 144 * 8 = 33408 B
    __shared__ int    shf[BT][N_COLS + 1];         // stride 23: conflict-free
    __shared__ float2 shred[8][32];
    __shared__ uchar2 shp[CHUNKSZ];

    const int tid   = threadIdx.x;
    const int lane  = tid & 31;
    const int warp  = tid >> 5;
    const int bbase = blockIdx.x * BT;
    const int p0    = blockIdx.y * CHUNKSZ;
    const int npair = min(N_PAIRS - p0, CHUNKSZ);

    // stage this chunk's LUT slice (contiguous, float4-coalesced)
    {
        const float4* __restrict__ src = (const float4*)(g_T + p0 * COMBO2);
        float4* dst = (float4*)slut;
        const int nf4 = npair * (COMBO2 / 4);      // <= 2088
        for (int e = tid; e < nf4; e += 256)
            dst[e] = __ldg(&src[e]);
    }

    // coalesced load of this block's 128 feats rows
    for (int e = tid; e < BT * N_COLS; e += 256) {
        const int row = e / N_COLS, col = e - row * N_COLS;
        const int b   = bbase + row;
        shf[row][col] = (b < B) ? feats[b * N_COLS + col] : 0;
    }

    // (i, j) byte table for this chunk's pairs
    if (tid < npair) {
        const int p = p0 + tid;
        int i = 0, r = p, c = N_COLS - 1;
        while (r >= c) { r -= c; ++i; --c; }
        shp[tid] = make_uchar2((unsigned char)i, (unsigned char)(i + 1 + r));
    }
    __syncthreads();

    const int subtile = warp & 3;            // which 32 batch elems
    const int stripe  = warp >> 2;           // pair stripe (0/1)
    const int brow    = subtile * 32 + lane; // 0..127

    float ax = 0.0f, ay = 0.0f;
#pragma unroll
    for (int t = stripe; t < CHUNKSZ; t += 2) {
        if (t < npair) {
            const uchar2 ij  = shp[t];
            const int    idx = shf[brow][ij.x] * EMB + shf[brow][ij.y];
            const float2 v   = slut[t * (EMB * EMB) + idx];
            ax += v.x;
            ay += v.y;
        }
    }

    shred[warp][lane] = make_float2(ax, ay);
    __syncthreads();

    if (warp < 4) {
        const float2 a = shred[warp][lane];
        const float2 c = shred[warp + 4][lane];
        const int b = bbase + warp * 32 + lane;
        if (b < B) {
            atomicAdd(&out[b * 2 + 0], a.x + c.x);
            atomicAdd(&out[b * 2 + 1], a.y + c.y);
        }
    }
}

// ---------------------------------------------------------------------------
// Launch: two kernels on the default stream (implicit ordering), graph-safe.
// Inputs (metadata order): feats(i32), tables(f32), W_small(f32),
//                          W_concat(f32), arch_weights(f32)
// ---------------------------------------------------------------------------
extern "C" void kernel_launch(void* const* d_in, const int* in_sizes, int n_in,
                              void* d_out, int out_size)
{
    const int*   feats   = (const int*)  d_in[0];
    const float* tables  = (const float*)d_in[1];
    const float* Wsmall  = (const float*)d_in[2];
    const float* Wconcat = (const float*)d_in[3];
    const float* aw      = (const float*)d_in[4];
    float*       out     = (float*)d_out;

    const int B = in_sizes[0] / N_COLS;   // 4096

    build_lut_kernel<<<N_PAIRS, COMBO2>>>(tables, Wsmall, Wconcat, aw, out, out_size);

    dim3 grid((B + BT - 1) / BT, NCHUNK); // 32 x 8 = 256 blocks
    accumulate_kernel<<<grid, 256>>>(feats, out, B);
}

// round 7
// speedup vs baseline: 1.1403x; 1.1403x over previous
#include <cuda_runtime.h>
#include <cuda_bf16.h>
#include <cstdint>

// Problem constants (fixed by the reference)
#define N_COLS  22
#define N_PAIRS 231
#define EMB     12
#define DVEC    64
#define N_PRIM  5
#define COMBO2  (EMB * EMB * 2)   // 288 floats per pair in the LUT
#define NCHUNK  4                 // pair-dimension split for kernel 2
#define CHUNKSZ ((N_PAIRS + NCHUNK - 1) / NCHUNK)   // 58
#define K1_PPB  2                 // pairs per block in kernel 1
#define K1_BLK  (K1_PPB * COMBO2) // 576 threads

// Pair index table, computed on host, passed by value (constant bank)
struct PairTab { uchar2 ij[N_PAIRS]; };

// Scratch: precomputed per-pair lookup table T[p][fi][fj][o]  (266 KB)
__device__ __align__(16) float g_T[N_PAIRS * COMBO2];

// ---------------------------------------------------------------------------
// Kernel 1: build T[p, fi, fj, o] = sum_d w_sel[p,o,d] * op_sel(ti[fi,d], tj[fj,d])
// 116 blocks x 576 threads: each block handles TWO pairs (one task per thread).
// float4 staging + float4 inner loop. Also zero-initializes out[].
// ---------------------------------------------------------------------------
#define ROWSTRIDE (DVEC + 4)      // 68 floats: float4-aligned, shifts banks by 4/row

__global__ __launch_bounds__(K1_BLK)
void build_lut_kernel(const float* __restrict__ tables,
                      const float* __restrict__ Wsmall,
                      const float* __restrict__ Wconcat,
                      const float* __restrict__ aw,
                      float* __restrict__ out, int outN,
                      const PairTab tab)
{
    const int half = threadIdx.x / COMBO2;          // 0 or 1
    const int task = threadIdx.x - half * COMBO2;   // 0..287
    const int p    = blockIdx.x * K1_PPB + half;
    const bool pv  = (p < N_PAIRS);

    // zero the output buffer (poisoned by harness); same-stream ordering makes
    // this visible to kernel 2's atomics
    {
        const int e = blockIdx.x * K1_BLK + threadIdx.x;
        if (e < outN) out[e] = 0.0f;
    }

    const int i = pv ? tab.ij[p].x : 0;
    const int j = pv ? tab.ij[p].y : 1;

    // selected primitive (arch_weights is exact one-hot of 0.0 / 1.0)
    int k = 0;
    if (pv) {
#pragma unroll
        for (int t = 0; t < N_PRIM; ++t)
            if (aw[p * N_PRIM + t] > 0.5f) k = t;
    }

    // stage the 12 candidate embedding vectors for columns i and j (float4)
    __shared__ float sh[K1_PPB][2][EMB * ROWSTRIDE];
    {
        const float4* __restrict__ t4 = (const float4*)tables;
        // each half stages its own pair's two tables: 2*12*16 = 384 float4
        for (int e = task; e < 2 * EMB * (DVEC / 4); e += COMBO2) {
            const int which = (e >= EMB * (DVEC / 4));
            const int e2  = e - which * EMB * (DVEC / 4);
            const int row = e2 >> 4, d4 = e2 & 15;
            const float4 v = __ldg(&t4[((which ? j : i) * EMB + row) * (DVEC / 4) + d4]);
            ((float4*)sh[half][which])[row * (ROWSTRIDE / 4) + d4] = v;
        }
    }
    __syncthreads();

    if (!pv) return;

    const int o     = task & 1;
    const int combo = task >> 1;            // fi*12 + fj
    const int fi    = combo / EMB;
    const int fj    = combo - fi * EMB;

    const float4* __restrict__ pi = (const float4*)&sh[half][0][fi * ROWSTRIDE];
    const float4* __restrict__ pj = (const float4*)&sh[half][1][fj * ROWSTRIDE];

    float acc = 0.0f;
    if (k == 4) {
        const float4* __restrict__ wa = (const float4*)(Wconcat + (p * 2 + o) * (2 * DVEC));
        const float4* __restrict__ wb = wa + (DVEC / 4);
#pragma unroll
        for (int d = 0; d < DVEC / 4; ++d) {
            const float4 a = pi[d], b = pj[d];
            const float4 u = __ldg(&wa[d]), v = __ldg(&wb[d]);
            acc += u.x * a.x + u.y * a.y + u.z * a.z + u.w * a.w;
            acc += v.x * b.x + v.y * b.y + v.z * b.z + v.w * b.w;
        }
    } else {
        const float4* __restrict__ w = (const float4*)(Wsmall + ((p * 4 + k) * 2 + o) * DVEC);
#pragma unroll
        for (int d = 0; d < DVEC / 4; ++d) {
            const float4 a = pi[d], b = pj[d];
            const float4 u = __ldg(&w[d]);
            float4 z;
            if (k == 0)      { z.x = a.x + b.x; z.y = a.y + b.y; z.z = a.z + b.z; z.w = a.w + b.w; }
            else if (k == 1) { z.x = a.x * b.x; z.y = a.y * b.y; z.z = a.z * b.z; z.w = a.w * b.w; }
            else if (k == 2) { z.x = fmaxf(a.x, b.x); z.y = fmaxf(a.y, b.y); z.z = fmaxf(a.z, b.z); z.w = fmaxf(a.w, b.w); }
            else             { z.x = fminf(a.x, b.x); z.y = fminf(a.y, b.y); z.z = fminf(a.z, b.z); z.w = fminf(a.w, b.w); }
            acc += u.x * z.x + u.y * z.y + u.z * z.z + u.w * z.w;
        }
    }
    g_T[p * COMBO2 + combo * 2 + o] = acc;
}

// ---------------------------------------------------------------------------
// Kernel 2: out[b, :] += sum_{p in chunk} T[p, f[i_p], f[j_p], :]
// grid = (B/32) x NCHUNK. lane = batch element (32/block); warp w of 8 strides
// its chunk's 58 pairs (<=8 independent unrolled gathers -> full MLP).
// All 32 lanes of a warp gather inside ONE pair's 1.15 KB LUT region
// (L1-coherent). Pair indices come from the constant-bank param table.
// Cross-warp SMEM reduce, then atomicAdd (out zeroed by kernel 1).
// ---------------------------------------------------------------------------
__global__ __launch_bounds__(256)
void accumulate_kernel(const int* __restrict__ feats,
                       float* __restrict__ out,
                       int B,
                       const PairTab tab)
{
    __shared__ int    shf[32][N_COLS + 1];   // stride 23: coprime with 32 banks
    __shared__ float2 shred[8][32];

    const int tid   = threadIdx.x;
    const int lane  = tid & 31;
    const int warp  = tid >> 5;
    const int bbase = blockIdx.x * 32;
    const int p0    = blockIdx.y * CHUNKSZ;
    const int npair = min(N_PAIRS - p0, CHUNKSZ);

    // coalesced, cooperative load of this block's 32 feats rows
    for (int e = tid; e < 32 * N_COLS; e += 256) {
        const int row = e / N_COLS, col = e - row * N_COLS;
        const int b   = bbase + row;
        shf[row][col] = (b < B) ? feats[b * N_COLS + col] : 0;
    }
    __syncthreads();

    const float2* __restrict__ T2 = (const float2*)g_T;
    float ax = 0.0f, ay = 0.0f;

    // warp w handles chunk-local pairs w, w+8, ... (<= 8 independent gathers)
#pragma unroll 8
    for (int t = warp; t < npair; t += 8) {
        const uchar2 ij = tab.ij[p0 + t];        // constant bank, uniform
        const int fi = shf[lane][ij.x];
        const int fj = shf[lane][ij.y];
        const float2 v = __ldg(&T2[(p0 + t) * (EMB * EMB) + fi * EMB + fj]);
        ax += v.x;
        ay += v.y;
    }

    shred[warp][lane] = make_float2(ax, ay);
    __syncthreads();

    if (warp == 0) {
        float sx = 0.0f, sy = 0.0f;
#pragma unroll
        for (int w = 0; w < 8; ++w) {
            const float2 s = shred[w][lane];
            sx += s.x;
            sy += s.y;
        }
        const int b = bbase + lane;
        if (b < B) {
            atomicAdd(&out[b * 2 + 0], sx);
            atomicAdd(&out[b * 2 + 1], sy);
        }
    }
}

// ---------------------------------------------------------------------------
// Launch: two kernels on the default stream (implicit ordering), graph-safe.
// Inputs (metadata order): feats(i32), tables(f32), W_small(f32),
//                          W_concat(f32), arch_weights(f32)
// ---------------------------------------------------------------------------
extern "C" void kernel_launch(void* const* d_in, const int* in_sizes, int n_in,
                              void* d_out, int out_size)
{
    const int*   feats   = (const int*)  d_in[0];
    const float* tables  = (const float*)d_in[1];
    const float* Wsmall  = (const float*)d_in[2];
    const float* Wconcat = (const float*)d_in[3];
    const float* aw      = (const float*)d_in[4];
    float*       out     = (float*)d_out;

    const int B = in_sizes[0] / N_COLS;   // 4096

    // host-side triu(N_COLS, 1) pair table -> constant-bank kernel param
    PairTab tab;
    {
        int p = 0;
        for (int i = 0; i < N_COLS; ++i)
            for (int j = i + 1; j < N_COLS; ++j, ++p)
                tab.ij[p] = make_uchar2((unsigned char)i, (unsigned char)j);
    }

    const int k1_grid = (N_PAIRS + K1_PPB - 1) / K1_PPB;   // 116
    build_lut_kernel<<<k1_grid, K1_BLK>>>(tables, Wsmall, Wconcat, aw,
                                          out, out_size, tab);

    dim3 grid((B + 31) / 32, NCHUNK);     // 128 x 4 = 512 blocks
    accumulate_kernel<<<grid, 256>>>(feats, out, B, tab);
}